// round 16
// baseline (speedup 1.0000x reference)
#include <cuda_runtime.h>
#include <math.h>
#include <stdint.h>

// Problem constants
#define B_   2
#define S_   2048
#define D_   1024
#define H_   16
#define DK_  64
#define BS_  (B_ * S_)   // 4096

// ---------------------------------------------------------------------------
// Device scratch (no allocations allowed -> __device__ globals)
// ---------------------------------------------------------------------------
__device__ float g_Q[B_ * H_ * S_ * DK_];     // [B,H,S,DK]  (tf32-rounded)
__device__ float g_K[B_ * H_ * S_ * DK_];
__device__ float g_V[B_ * H_ * S_ * DK_];
__device__ float g_ctx[B_ * S_ * D_];         // [B,S,D]     (tf32-rounded)
__device__ float g_proj[B_ * S_ * D_];        // out-proj result (exact fp32)
__device__ float g_rW[4 * D_ * D_];           // rounded wq,wk,wv,wo
__device__ float g_rX[3 * BS_ * D_];          // rounded query,key,value

// ---------------------------------------------------------------------------
// tf32 + cp.async + ldmatrix helpers
// ---------------------------------------------------------------------------
__device__ __forceinline__ uint32_t f2tf(float f) {
    uint32_t u;
    asm("cvt.rna.tf32.f32 %0, %1;" : "=r"(u) : "f"(f));
    return u;
}
__device__ __forceinline__ uint4 f2tf4(float4 v) {
    uint4 u;
    u.x = f2tf(v.x); u.y = f2tf(v.y); u.z = f2tf(v.z); u.w = f2tf(v.w);
    return u;
}
__device__ __forceinline__ void cp16(uint32_t dst, const void* src) {
    asm volatile("cp.async.cg.shared.global [%0], [%1], 16;\n"
                 :: "r"(dst), "l"(src));
}
__device__ __forceinline__ void cp_commit() {
    asm volatile("cp.async.commit_group;\n");
}
template <int N>
__device__ __forceinline__ void cp_wait() {
    asm volatile("cp.async.wait_group %0;\n" :: "n"(N));
}
// ldmatrix x4: four 8-row x 16-byte matrices; lane groups 0-7/8-15/16-23/24-31
// supply the row addresses of matrices 0..3.
__device__ __forceinline__ void ldsm4(uint32_t& d0, uint32_t& d1,
                                      uint32_t& d2, uint32_t& d3, uint32_t addr) {
    asm volatile("ldmatrix.sync.aligned.m8n8.x4.shared.b16 {%0,%1,%2,%3}, [%4];"
                 : "=r"(d0), "=r"(d1), "=r"(d2), "=r"(d3) : "r"(addr));
}
// D(16x8,f32) += A(16x8,tf32,row) * B(8x8,tf32,col)
__device__ __forceinline__ void mma_tf32(float& d0, float& d1, float& d2, float& d3,
                                         uint32_t a0, uint32_t a1, uint32_t a2, uint32_t a3,
                                         uint32_t b0, uint32_t b1) {
    asm volatile(
        "mma.sync.aligned.m16n8k8.row.col.f32.tf32.tf32.f32 "
        "{%0,%1,%2,%3}, {%4,%5,%6,%7}, {%8,%9}, {%0,%1,%2,%3};\n"
        : "+f"(d0), "+f"(d1), "+f"(d2), "+f"(d3)
        : "r"(a0), "r"(a1), "r"(a2), "r"(a3), "r"(b0), "r"(b1));
}

// ---------------------------------------------------------------------------
// One merged tf32 rounding pass over all 7 tensors (z selects tensor).
// ---------------------------------------------------------------------------
__global__ void round_all(const float* __restrict__ wq, const float* __restrict__ wk,
                          const float* __restrict__ wv, const float* __restrict__ wo,
                          const float* __restrict__ xq, const float* __restrict__ xk,
                          const float* __restrict__ xv,
                          float* __restrict__ rW, float* __restrict__ rX)
{
    const int z = blockIdx.z;
    const int NW = D_ * D_;
    const int NX = BS_ * D_;
    const int n  = (z < 4) ? NW : NX;
    const int i  = (blockIdx.x * blockDim.x + threadIdx.x) * 4;
    if (i >= n) return;
    const float* src;
    float* dst;
    switch (z) {
        case 0: src = wq; dst = rW;                  break;
        case 1: src = wk; dst = rW + 1 * (size_t)NW; break;
        case 2: src = wv; dst = rW + 2 * (size_t)NW; break;
        case 3: src = wo; dst = rW + 3 * (size_t)NW; break;
        case 4: src = xq; dst = rX;                  break;
        case 5: src = xk; dst = rX + 1 * (size_t)NX; break;
        default: src = xv; dst = rX + 2 * (size_t)NX; break;
    }
    uint4 u = f2tf4(*(const float4*)(src + i));
    *(float4*)(dst + i) = make_float4(__uint_as_float(u.x), __uint_as_float(u.y),
                                      __uint_as_float(u.z), __uint_as_float(u.w));
}

// ---------------------------------------------------------------------------
// tf32 tensor-core GEMM body: Y[m][n] = sum_k A[m][k]*W[n][k] + bias[n]
// CTA 128x128, 256 thr, warp tile 64x32. k32 chunks, 3-stage cp.async with
// cp_wait<1> (each prefetch has TWO chunks of compute to land). ldmatrix
// fragment loads. smem pitch 36 (conflict-free). Dynamic smem 110.6 KB,
// 2 CTAs/SM.
// ---------------------------------------------------------------------------
#define GP 36   // 32 data + 4 pad
#define GBUF (128 * GP * 4)            // one stage of one operand, bytes
#define GSTAGES 3
#define GEMM_SMEM (2 * GSTAGES * GBUF) // 110592 bytes

template <int MODE>
__device__ __forceinline__
void gemm_body(const float* __restrict__ A, const float* __restrict__ W,
               const float* __restrict__ bias, float* __restrict__ out,
               uint32_t* As /* [GSTAGES][128*GP] */,
               uint32_t* Bs /* [GSTAGES][128*GP] */)
{
    const int tid  = threadIdx.x;
    const int lane = tid & 31;
    const int w    = tid >> 5;
    const int wm   = w & 1;
    const int wn   = w >> 1;
    const int row0 = blockIdx.y * 128;
    const int col0 = blockIdx.x * 128;
    const int r = lane >> 2;
    const int j = lane & 3;

    const int lrow = tid & 127;
    const int lkq  = (tid >> 7) << 4;   // 0 or 16

    const float* Aptr = A + (size_t)(row0 + lrow) * D_ + lkq;
    const float* Wptr = W + (size_t)(col0 + lrow) * D_ + lkq;

    uint32_t sA[GSTAGES], sB[GSTAGES];
#pragma unroll
    for (int s = 0; s < GSTAGES; ++s) {
        sA[s] = (uint32_t)__cvta_generic_to_shared(&As[s * 128 * GP + lrow * GP + lkq]);
        sB[s] = (uint32_t)__cvta_generic_to_shared(&Bs[s * 128 * GP + lrow * GP + lkq]);
    }

    // ldmatrix lane addresses (byte, stage 0)
    // A (x4 per mt): rows wm*64 + mt*16 + (lane&15), k-col (lane>>4)*4
    const uint32_t aBase = (uint32_t)__cvta_generic_to_shared(As) +
        (((wm * 64 + (lane & 15)) * GP + ((lane >> 4) << 2)) << 2);
    // B (x4 per nt-pair p): rows wn*32 + p*16 + ((lane>>4)&1)*8 + (lane&7),
    //                       k-col ((lane>>3)&1)*4
    const uint32_t bBase = (uint32_t)__cvta_generic_to_shared(Bs) +
        (((wn * 32 + (((lane >> 4) & 1) << 3) + (lane & 7)) * GP +
          (((lane >> 3) & 1) << 2)) << 2);

    float acc[4][4][4];
#pragma unroll
    for (int mt = 0; mt < 4; ++mt)
#pragma unroll
        for (int nt = 0; nt < 4; ++nt)
#pragma unroll
            for (int c = 0; c < 4; ++c) acc[mt][nt][c] = 0.0f;

    // prologue: stage chunks 0,1 into stages 0,1
#pragma unroll
    for (int t = 0; t < 2; ++t) {
#pragma unroll
        for (int q = 0; q < 4; ++q) {
            cp16(sA[t] + q * 16, Aptr + t * 32 + q * 4);
            cp16(sB[t] + q * 16, Wptr + t * 32 + q * 4);
        }
        cp_commit();
    }

    constexpr int TILES = D_ / 32;   // 32
    int cur = 0;                     // stage holding chunk t
    for (int t = 0; t < TILES; ++t) {
        if (t < TILES - 1) cp_wait<1>(); else cp_wait<0>();
        __syncthreads();   // chunk t visible; all warps done with iter t-1

        if (t + 2 < TILES) {
            const int nb = (cur + 2 >= GSTAGES) ? cur + 2 - GSTAGES : cur + 2;
            const float* a  = Aptr + (t + 2) * 32;
            const float* wv = Wptr + (t + 2) * 32;
#pragma unroll
            for (int q = 0; q < 4; ++q) {
                cp16(sA[nb] + q * 16, a + q * 4);
                cp16(sB[nb] + q * 16, wv + q * 4);
            }
            cp_commit();
        }

        const uint32_t aBuf = aBase + cur * GBUF;
        const uint32_t bBuf = bBase + cur * GBUF;
#pragma unroll
        for (int ss = 0; ss < 4; ++ss) {
            uint32_t af[4][4];
#pragma unroll
            for (int mt = 0; mt < 4; ++mt)
                ldsm4(af[mt][0], af[mt][1], af[mt][2], af[mt][3],
                      aBuf + mt * (16 * GP * 4) + ss * 32);
            uint32_t bf[4][2];
#pragma unroll
            for (int p = 0; p < 2; ++p)
                ldsm4(bf[2 * p][0], bf[2 * p][1], bf[2 * p + 1][0], bf[2 * p + 1][1],
                      bBuf + p * (16 * GP * 4) + ss * 32);
#pragma unroll
            for (int nt = 0; nt < 4; ++nt)
#pragma unroll
                for (int mt = 0; mt < 4; ++mt)
                    mma_tf32(acc[mt][nt][0], acc[mt][nt][1], acc[mt][nt][2], acc[mt][nt][3],
                             af[mt][0], af[mt][1], af[mt][2], af[mt][3],
                             bf[nt][0], bf[nt][1]);
        }
        cur = (cur + 1 >= GSTAGES) ? 0 : cur + 1;
        // no trailing barrier: next iteration's top barrier orders stage reuse
    }

    // epilogue
#pragma unroll
    for (int mt = 0; mt < 4; ++mt) {
        const int gr = row0 + wm * 64 + mt * 16 + r;
#pragma unroll
        for (int nt = 0; nt < 4; ++nt) {
            const int gc = col0 + wn * 32 + nt * 8 + 2 * j;
            const float2 bb = *(const float2*)&bias[gc];
            float2 v0 = make_float2(acc[mt][nt][0] + bb.x, acc[mt][nt][1] + bb.y);
            float2 v1 = make_float2(acc[mt][nt][2] + bb.x, acc[mt][nt][3] + bb.y);
            if (MODE == 0) {
                *(float2*)&out[(size_t)gr * D_ + gc]       = v0;
                *(float2*)&out[(size_t)(gr + 8) * D_ + gc] = v1;
            } else {
                // round to tf32 (consumed by attention MMAs)
                v0 = make_float2(__uint_as_float(f2tf(v0.x)), __uint_as_float(f2tf(v0.y)));
                v1 = make_float2(__uint_as_float(f2tf(v1.x)), __uint_as_float(f2tf(v1.y)));
                const int h  = gc >> 6;
                const int dk = gc & 63;
                const int b0i = gr >> 11, s0 = gr & (S_ - 1);
                const int gr1 = gr + 8;
                const int b1i = gr1 >> 11, s1 = gr1 & (S_ - 1);
                *(float2*)&out[(((size_t)(b0i * H_ + h) * S_) + s0) * DK_ + dk] = v0;
                *(float2*)&out[(((size_t)(b1i * H_ + h) * S_) + s1) * DK_ + dk] = v1;
            }
        }
    }
}

// wo projection: single GEMM, row-major fp32 out
__global__ __launch_bounds__(256, 2)
void gemm_tc0(const float* __restrict__ A, const float* __restrict__ W,
              const float* __restrict__ bias, float* __restrict__ out)
{
    extern __shared__ uint32_t gsm[];
    gemm_body<0>(A, W, bias, out, gsm, gsm + GSTAGES * 128 * GP);
}

// QKV projections merged: blockIdx.z selects {q,k,v} -> dense wave packing
__global__ __launch_bounds__(256, 2)
void gemm_qkv(const float* __restrict__ X, const float* __restrict__ W4,
              const float* __restrict__ bq, const float* __restrict__ bk,
              const float* __restrict__ bv,
              float* __restrict__ oq, float* __restrict__ ok,
              float* __restrict__ ov)
{
    extern __shared__ uint32_t gsm[];
    const int z = blockIdx.z;
    const size_t NX = (size_t)BS_ * D_;
    const size_t NW = (size_t)D_ * D_;
    const float* A    = X  + z * NX;
    const float* W    = W4 + z * NW;
    const float* bias = (z == 0) ? bq : (z == 1) ? bk : bv;
    float*       out  = (z == 0) ? oq : (z == 1) ? ok : ov;
    gemm_body<1>(A, W, bias, out, gsm, gsm + GSTAGES * 128 * GP);
}

// ---------------------------------------------------------------------------
// Flash attention, tf32 tensor cores, single-buffered K/V, 2 CTAs/SM.
// CTA 256 thr (8 warps), Q tile 128 rows, K tile 64 keys; warp = one m16 slice.
// smem (103 KB): Qs[128][68], Ks[64][68], Vs[64][72], Ps[128][68].
// Q/K/P fragments via ldmatrix; V B-frags scalar LDS.
// ---------------------------------------------------------------------------
#define AP 68
#define VP 72

__global__ __launch_bounds__(256, 2)
void attn_tc(const float* __restrict__ cplx, const float* __restrict__ cpen_p)
{
    extern __shared__ uint32_t smem[];
    uint32_t* Qs = smem;                 // 128*AP
    uint32_t* Ks = Qs + 128 * AP;        // 64*AP
    uint32_t* Vs = Ks + 64 * AP;         // 64*VP
    uint32_t* Ps = Vs + 64 * VP;         // 128*AP

    const int tid  = threadIdx.x;
    const int lane = tid & 31;
    const int w    = tid >> 5;
    const int r    = lane >> 2;
    const int j    = lane & 3;
    const int rb   = w * 16;              // warp row base (0..112)

    const int qt = (gridDim.x - 1) - blockIdx.x;   // heavy tiles first
    const int bh = blockIdx.y;
    const int b  = bh >> 4;
    const int h  = bh & 15;
    const float cpen = __ldg(cpen_p);

    const float* Qg = g_Q + (size_t)bh * S_ * DK_;
    const float* Kg = g_K + (size_t)bh * S_ * DK_;
    const float* Vg = g_V + (size_t)bh * S_ * DK_;

    // Q staging: 256 thr, each 32 floats of one row
    const int qrow  = tid >> 1;           // 0..127
    const int qhalf = (tid & 1) * 32;
    const uint32_t qdst = (uint32_t)__cvta_generic_to_shared(&Qs[qrow * AP + qhalf]);

    // K/V staging: 256 thr, each 16 floats of one row
    const int krow = tid >> 2;            // 0..63
    const int kq   = (tid & 3) * 16;
    const uint32_t kdst = (uint32_t)__cvta_generic_to_shared(&Ks[krow * AP + kq]);
    const uint32_t vdst = (uint32_t)__cvta_generic_to_shared(&Vs[krow * VP + kq]);

    // ldmatrix lane addresses (byte)
    const uint32_t qLm = (uint32_t)__cvta_generic_to_shared(Qs) +
        (((rb + (lane & 15)) * AP + ((lane >> 4) << 2)) << 2);
    const uint32_t pLm = (uint32_t)__cvta_generic_to_shared(Ps) +
        (((rb + (lane & 15)) * AP + ((lane >> 4) << 2)) << 2);
    const uint32_t kLm = (uint32_t)__cvta_generic_to_shared(Ks) +
        ((((((lane >> 4) & 1) << 3) + (lane & 7)) * AP +
          (((lane >> 3) & 1) << 2)) << 2);

    auto stage_kv = [&](int kt) {
        const float* ks = Kg + (size_t)(kt * 64 + krow) * DK_ + kq;
        const float* vs = Vg + (size_t)(kt * 64 + krow) * DK_ + kq;
#pragma unroll
        for (int q = 0; q < 4; ++q) {
            cp16(kdst + q * 16, ks + q * 4);
            cp16(vdst + q * 16, vs + q * 4);
        }
    };

    // prologue: Q tile + first K/V tile
    {
        const float* qs = Qg + (size_t)(qt * 128 + qrow) * DK_ + qhalf;
#pragma unroll
        for (int q = 0; q < 8; ++q) cp16(qdst + q * 16, qs + q * 4);
        stage_kv(0);
        cp_commit();
    }

    float o[8][4];
    float m_lo = -1e30f, m_hi = -1e30f, l_lo = 0.0f, l_hi = 0.0f;
#pragma unroll
    for (int nt = 0; nt < 8; ++nt)
#pragma unroll
        for (int c = 0; c < 4; ++c) o[nt][c] = 0.0f;

    const int nkt = 2 * qt + 2;
    for (int kt = 0; kt < nkt; ++kt) {
        cp_wait<0>();
        __syncthreads();   // staged K/V (+Q on iter 0) visible to all warps

        // ---- S = Q K^T  (warp: 16 rows x 64 keys) ----
        float s[8][4];
#pragma unroll
        for (int nt = 0; nt < 8; ++nt)
#pragma unroll
            for (int c = 0; c < 4; ++c) s[nt][c] = 0.0f;

#pragma unroll
        for (int ks = 0; ks < 8; ++ks) {
            uint32_t a0, a1, a2, a3;
            ldsm4(a0, a1, a2, a3, qLm + ks * 32);
            uint32_t kb[8][2];
#pragma unroll
            for (int p = 0; p < 4; ++p)
                ldsm4(kb[2 * p][0], kb[2 * p][1], kb[2 * p + 1][0], kb[2 * p + 1][1],
                      kLm + p * (16 * AP * 4) + ks * 32);
#pragma unroll
            for (int nt = 0; nt < 8; ++nt)
                mma_tf32(s[nt][0], s[nt][1], s[nt][2], s[nt][3],
                         a0, a1, a2, a3, kb[nt][0], kb[nt][1]);
        }

        // ---- scale + penalty + causal mask ----
        const int rowg_lo = qt * 128 + rb + r;
        const int rowg_hi = rowg_lo + 8;
#pragma unroll
        for (int nt = 0; nt < 8; ++nt) {
            const int colg = kt * 64 + nt * 8 + 2 * j;
            const float2 cv = *(const float2*)&cplx[b * S_ + colg];
            const float p0 = cpen * cv.x, p1 = cpen * cv.y;
            s[nt][0] = s[nt][0] * 0.125f - p0;
            s[nt][1] = s[nt][1] * 0.125f - p1;
            s[nt][2] = s[nt][2] * 0.125f - p0;
            s[nt][3] = s[nt][3] * 0.125f - p1;
            if (kt >= 2 * qt) {          // (possibly) diagonal k-tile
                if (colg     > rowg_lo) s[nt][0] = -1e9f;
                if (colg + 1 > rowg_lo) s[nt][1] = -1e9f;
                if (colg     > rowg_hi) s[nt][2] = -1e9f;
                if (colg + 1 > rowg_hi) s[nt][3] = -1e9f;
            }
        }

        // ---- online softmax ----
        float mx_lo = -1e30f, mx_hi = -1e30f;
#pragma unroll
        for (int nt = 0; nt < 8; ++nt) {
            mx_lo = fmaxf(mx_lo, fmaxf(s[nt][0], s[nt][1]));
            mx_hi = fmaxf(mx_hi, fmaxf(s[nt][2], s[nt][3]));
        }
        mx_lo = fmaxf(mx_lo, __shfl_xor_sync(0xffffffffu, mx_lo, 1));
        mx_lo = fmaxf(mx_lo, __shfl_xor_sync(0xffffffffu, mx_lo, 2));
        mx_hi = fmaxf(mx_hi, __shfl_xor_sync(0xffffffffu, mx_hi, 1));
        mx_hi = fmaxf(mx_hi, __shfl_xor_sync(0xffffffffu, mx_hi, 2));

        const float nm_lo = fmaxf(m_lo, mx_lo);
        const float nm_hi = fmaxf(m_hi, mx_hi);
        const float al_lo = __expf(m_lo - nm_lo);
        const float al_hi = __expf(m_hi - nm_hi);
        m_lo = nm_lo; m_hi = nm_hi;

        float sum_lo = 0.0f, sum_hi = 0.0f;
#pragma unroll
        for (int nt = 0; nt < 8; ++nt) {
            s[nt][0] = __expf(s[nt][0] - nm_lo);
            s[nt][1] = __expf(s[nt][1] - nm_lo);
            s[nt][2] = __expf(s[nt][2] - nm_hi);
            s[nt][3] = __expf(s[nt][3] - nm_hi);
            sum_lo += s[nt][0] + s[nt][1];
            sum_hi += s[nt][2] + s[nt][3];
            uint2 plo = make_uint2(f2tf(s[nt][0]), f2tf(s[nt][1]));
            uint2 phi = make_uint2(f2tf(s[nt][2]), f2tf(s[nt][3]));
            *(uint2*)&Ps[(rb + r) * AP + nt * 8 + 2 * j]     = plo;
            *(uint2*)&Ps[(rb + r + 8) * AP + nt * 8 + 2 * j] = phi;
        }
        sum_lo += __shfl_xor_sync(0xffffffffu, sum_lo, 1);
        sum_lo += __shfl_xor_sync(0xffffffffu, sum_lo, 2);
        sum_hi += __shfl_xor_sync(0xffffffffu, sum_hi, 1);
        sum_hi += __shfl_xor_sync(0xffffffffu, sum_hi, 2);
        l_lo = l_lo * al_lo + sum_lo;
        l_hi = l_hi * al_hi + sum_hi;

#pragma unroll
        for (int nt = 0; nt < 8; ++nt) {
            o[nt][0] *= al_lo; o[nt][1] *= al_lo;
            o[nt][2] *= al_hi; o[nt][3] *= al_hi;
        }
        __syncwarp();   // P (warp-private rows) visible within warp

        // ---- O += P V  (V row-major: B[k=key][n=d], pitch 72) ----
#pragma unroll
        for (int ks = 0; ks < 8; ++ks) {
            uint32_t a0, a1, a2, a3;
            ldsm4(a0, a1, a2, a3, pLm + ks * 32);
            const int krow0 = (ks * 8 + j) * VP;
            const int krow1 = (ks * 8 + j + 4) * VP;
#pragma unroll
            for (int nt = 0; nt < 8; ++nt) {
                uint32_t b0 = Vs[krow0 + nt * 8 + r];
                uint32_t b1 = Vs[krow1 + nt * 8 + r];
                mma_tf32(o[nt][0], o[nt][1], o[nt][2], o[nt][3], a0, a1, a2, a3, b0, b1);
            }
        }

        // all warps done reading Ks/Vs before restaging
        __syncthreads();
        if (kt + 1 < nkt) { stage_kv(kt + 1); cp_commit(); }
    }

    // ---- epilogue (ctx written tf32-rounded for the Wo GEMM) ----
    const float inv_lo = 1.0f / l_lo;
    const float inv_hi = 1.0f / l_hi;
    const int row_lo = qt * 128 + rb + r;
    const int row_hi = row_lo + 8;
#pragma unroll
    for (int nt = 0; nt < 8; ++nt) {
        const int gc = h * DK_ + nt * 8 + 2 * j;
        *(float2*)&g_ctx[(size_t)(b * S_ + row_lo) * D_ + gc] =
            make_float2(__uint_as_float(f2tf(o[nt][0] * inv_lo)),
                        __uint_as_float(f2tf(o[nt][1] * inv_lo)));
        *(float2*)&g_ctx[(size_t)(b * S_ + row_hi) * D_ + gc] =
            make_float2(__uint_as_float(f2tf(o[nt][2] * inv_hi)),
                        __uint_as_float(f2tf(o[nt][3] * inv_hi)));
    }
}

// ---------------------------------------------------------------------------
// LayerNorm over D=1024 with residual add: out = LN(g_proj + query)*g + b
// ---------------------------------------------------------------------------
__global__ __launch_bounds__(256)
void ln_resid(const float* __restrict__ resid, const float* __restrict__ gamma,
              const float* __restrict__ beta, float* __restrict__ out)
{
    __shared__ float rs[8], rq[8];
    const int row = blockIdx.x;
    const int tid = threadIdx.x;

    const float* xr = g_proj + (size_t)row * D_;
    const float* rr = resid  + (size_t)row * D_;

    float4 a = *(const float4*)&xr[tid * 4];
    float4 r = *(const float4*)&rr[tid * 4];
    float x0 = a.x + r.x, x1 = a.y + r.y, x2 = a.z + r.z, x3 = a.w + r.w;

    float s  = x0 + x1 + x2 + x3;
    float sq = x0 * x0 + x1 * x1 + x2 * x2 + x3 * x3;
#pragma unroll
    for (int off = 16; off >= 1; off >>= 1) {
        s  += __shfl_xor_sync(0xffffffffu, s,  off);
        sq += __shfl_xor_sync(0xffffffffu, sq, off);
    }
    const int wid = tid >> 5;
    if ((tid & 31) == 0) { rs[wid] = s; rq[wid] = sq; }
    __syncthreads();
    float tot = 0.0f, totq = 0.0f;
#pragma unroll
    for (int ww = 0; ww < 8; ++ww) { tot += rs[ww]; totq += rq[ww]; }

    const float mean = tot * (1.0f / D_);
    const float var  = totq * (1.0f / D_) - mean * mean;
    const float rstd = rsqrtf(var + 1e-5f);

    float4 g = *(const float4*)&gamma[tid * 4];
    float4 be = *(const float4*)&beta[tid * 4];
    float4 oo;
    oo.x = (x0 - mean) * rstd * g.x + be.x;
    oo.y = (x1 - mean) * rstd * g.y + be.y;
    oo.z = (x2 - mean) * rstd * g.z + be.z;
    oo.w = (x3 - mean) * rstd * g.w + be.w;
    *(float4*)&out[(size_t)row * D_ + tid * 4] = oo;
}

// ---------------------------------------------------------------------------
// kernel_launch
// ---------------------------------------------------------------------------
extern "C" void kernel_launch(void* const* d_in, const int* in_sizes, int n_in,
                              void* d_out, int out_size)
{
    (void)in_sizes; (void)n_in; (void)out_size;

    const float* query = (const float*)d_in[0];
    const float* key   = (const float*)d_in[1];
    const float* value = (const float*)d_in[2];
    const float* cplx  = (const float*)d_in[3];
    // d_in[4] = mask (bool tril) — deterministic, applied analytically
    const float* wq = (const float*)d_in[5];
    const float* bq = (const float*)d_in[6];
    const float* wk = (const float*)d_in[7];
    const float* bk = (const float*)d_in[8];
    const float* wv = (const float*)d_in[9];
    const float* bv = (const float*)d_in[10];
    const float* wo = (const float*)d_in[11];
    const float* bo = (const float*)d_in[12];
    const float* lng = (const float*)d_in[13];
    const float* lnb = (const float*)d_in[14];
    const float* cpen = (const float*)d_in[15];
    float* out = (float*)d_out;

    void *pQ, *pK, *pV, *pCtx, *pProj, *pRW, *pRX;
    cudaGetSymbolAddress(&pQ,    g_Q);
    cudaGetSymbolAddress(&pK,    g_K);
    cudaGetSymbolAddress(&pV,    g_V);
    cudaGetSymbolAddress(&pCtx,  g_ctx);
    cudaGetSymbolAddress(&pProj, g_proj);
    cudaGetSymbolAddress(&pRW,   g_rW);
    cudaGetSymbolAddress(&pRX,   g_rX);
    float* rW = (float*)pRW;
    float* rX = (float*)pRX;

    const int ATTN_SMEM = (128 * AP + 64 * AP + 64 * VP + 128 * AP) * 4; // 105472
    cudaFuncSetAttribute(attn_tc, cudaFuncAttributeMaxDynamicSharedMemorySize,
                         ATTN_SMEM);
    cudaFuncSetAttribute(gemm_qkv, cudaFuncAttributeMaxDynamicSharedMemorySize,
                         GEMM_SMEM);
    cudaFuncSetAttribute(gemm_tc0, cudaFuncAttributeMaxDynamicSharedMemorySize,
                         GEMM_SMEM);

    // ---- pre-round weights & activations to tf32 (one merged launch) ----
    const int NX = BS_ * D_;      // 4 M
    dim3 gr(NX / 1024, 1, 7);
    round_all<<<gr, 256>>>(wq, wk, wv, wo, query, key, value, rW, rX);

    // Q/K/V projections merged into one launch (dense wave packing)
    dim3 gg3(D_ / 128, BS_ / 128, 3);   // (8, 32, 3)
    gemm_qkv<<<gg3, 256, GEMM_SMEM>>>(rX, rW, bq, bk, bv,
                                      (float*)pQ, (float*)pK, (float*)pV);

    // Flash attention -> g_ctx (tf32-rounded)
    dim3 ga(S_ / 128, B_ * H_);     // (16, 32)
    attn_tc<<<ga, 256, ATTN_SMEM>>>(cplx, cpen);

    // Output projection -> g_proj (exact fp32)
    const int NW = D_ * D_;
    dim3 gg(D_ / 128, BS_ / 128);   // (8, 32)
    gemm_tc0<<<gg, 256, GEMM_SMEM>>>((const float*)pCtx, rW + 3 * (size_t)NW,
                                     bo, (float*)pProj);

    // Residual + LayerNorm -> d_out
    ln_resid<<<BS_, 256>>>(query, lng, lnb, out);
}